// round 15
// baseline (speedup 1.0000x reference)
#include <cuda_runtime.h>
#include <cstdint>

// ---------------------------------------------------------------------------
// SpikingAttention: adaptive-LIF (LSNN) scans + WTA pseudo-softmax
// B=32, T=1000, D=512, U=512
// Single fused kernel, 256-thread blocks:
//   Blocks 0..31   : k lsnn   (one population per block, 2 neurons/thread)
//   Blocks 32..63  : q lsnn
//   Blocks 64..95  : v lsnn
//   Blocks 96..127 : wta
//   Blocks 128..159: att
//   Blocks 160..3159: GEMM tiles (8x8 f32x2/thread)
// 5-stage x 32-batch pipeline; handoffs via self-validating 64-bit words
// (seq<<32|mask, st/ld.relaxed.gpu) — no store drains on the critical path.
// ---------------------------------------------------------------------------

#define ALPHA 0.9f
#define RHO   0.995f
#define BETA  1.6f

#define NB 32
#define NT 1000
#define NU 512
#define MTOT (NB*NT)

#define OUT1_OFF 0ull
#define OUT2_OFF 16384000ull
#define OUT3_OFF 114688000ull
#define OUT4_OFF 180224000ull

__device__ float              g_xT[512ll * MTOT];        // x transposed: [k][t*32+b]
__device__ float              g_I[3ll * MTOT * NU];      // [pop][t*32+b][u]
__device__ unsigned long long g_spk64[3ll * MTOT * 16];  // [pop][b][t][16]: seq<<32|mask
__device__ unsigned long long g_zA64[(long long)MTOT * 16];
__device__ int                g_chunk[250];              // GEMM chunk completion (12)

// ---------------------------------------------------------------------------
__device__ __forceinline__ int ld_acquire(const int* p) {
    int v;
    asm volatile("ld.acquire.gpu.global.s32 %0, [%1];" : "=r"(v) : "l"(p) : "memory");
    return v;
}
__device__ __forceinline__ void red_release_add(int* p, int v) {
    asm volatile("red.release.gpu.global.add.s32 [%0], %1;" :: "l"(p), "r"(v) : "memory");
}
__device__ __forceinline__ void spin_ge(const int* p, int want) {
    while (ld_acquire(p) < want) { }
}

// self-validating mask word: high 32 = seq (t+1), low 32 = mask
__device__ __forceinline__ void push_word(unsigned long long* p, unsigned seq, unsigned mask) {
    unsigned long long v = ((unsigned long long)seq << 32) | (unsigned long long)mask;
    asm volatile("st.relaxed.gpu.global.u64 [%0], %1;" :: "l"(p), "l"(v) : "memory");
}
__device__ __forceinline__ unsigned poll_word(const unsigned long long* p, unsigned seq) {
    unsigned long long v;
    do {
        asm volatile("ld.relaxed.gpu.global.u64 %0, [%1];" : "=l"(v) : "l"(p) : "memory");
    } while ((unsigned)(v >> 32) != seq);
    return (unsigned)v;
}

#define FMA_F32X2(acc, a, b) \
    asm("fma.rn.f32x2 %0, %1, %2, %0;" : "+l"(acc) : "l"(a), "l"(b))
#define PACK_DUP2(out, f) \
    asm("mov.b64 %0, {%1, %1};" : "=l"(out) : "f"(f))

#define CP_ASYNC16(smem_addr, gptr) \
    asm volatile("cp.async.cg.shared.global [%0], [%1], 16;" :: "r"(smem_addr), "l"(gptr))
#define CP_COMMIT()  asm volatile("cp.async.commit_group;")
#define CP_WAIT(N)   asm volatile("cp.async.wait_group %0;" :: "n"(N))

__device__ __forceinline__ unsigned smem_u32(const void* p) {
    return (unsigned)__cvta_generic_to_shared(p);
}

// ---------------------------------------------------------------------------
// Transpose: x[b][t][k] -> xT[k][t*32+b]. grid (1000, 4), 256 threads.
// ---------------------------------------------------------------------------
__global__ __launch_bounds__(256) void transpose_kernel(const float* __restrict__ x)
{
    __shared__ float S[32][132];
    const int t  = blockIdx.x;
    const int kc = blockIdx.y;
    const int tid = threadIdx.x;
#pragma unroll
    for (int i = 0; i < 4; i++) {
        int f = i * 256 + tid;
        int b = f >> 5;
        int c4 = f & 31;
        float4 v = *(const float4*)(x + ((size_t)b * 1000 + t) * 512 + kc * 128 + c4 * 4);
        *(float4*)&S[b][c4 * 4] = v;
    }
    __syncthreads();
#pragma unroll
    for (int i = 0; i < 4; i++) {
        int f = i * 256 + tid;
        int kk = f >> 3;
        int c = f & 7;
        float4 v = make_float4(S[c * 4 + 0][kk], S[c * 4 + 1][kk],
                               S[c * 4 + 2][kk], S[c * 4 + 3][kk]);
        *(float4*)(g_xT + (size_t)(kc * 128 + kk) * MTOT + t * 32 + c * 4) = v;
    }
}

// reset: zero seq fields + chunk counters (stale seqs across graph replays).
__global__ void reset_kernel()
{
    const long long N1 = 3ll * MTOT * 16;
    const long long N2 = (long long)MTOT * 16;
    long long gid = (long long)blockIdx.x * blockDim.x + threadIdx.x;
    long long stride = (long long)gridDim.x * blockDim.x;
    for (long long i = gid; i < N1; i += stride) g_spk64[i] = 0ull;
    for (long long i = gid; i < N2; i += stride) g_zA64[i] = 0ull;
    if (gid < 250) g_chunk[gid] = 0;
}

// ---------------------------------------------------------------------------
struct GemmSmem {
    float As[2][16][128];
    float Bs[2][16][128];
};
struct ScanSmem {
    unsigned mask[16];     // lsnn own spikes
    unsigned maskZ[16];    // wta zA
    unsigned maskR[16];    // att own spikes
    float red[8];
    int tot;
    unsigned short list[1600];
};

// ---------------------------------------------------------------------------
__device__ __forceinline__ int build_list(unsigned m, int bias,
                                          unsigned short* list, int list_off)
{
    const int lane = threadIdx.x & 31;
    int c = __popc(m);
    int inc = c;
#pragma unroll
    for (int o = 1; o < 32; o <<= 1) {
        int v = __shfl_up_sync(0xffffffffu, inc, o);
        if (lane >= o) inc += v;
    }
    int off  = list_off + inc - c;
    int base = bias + lane * 32;
    while (m) {
        int j = __ffs((int)m) - 1;
        list[off++] = (unsigned short)(base + j);
        m &= (m - 1);
    }
    return __shfl_sync(0xffffffffu, inc, 31);
}

// 8-wide batched dual-neuron gather (list padded with >=8 zeros past n)
__device__ __forceinline__ void gather8d(const float* __restrict__ W,
                                         const unsigned short* list, int n,
                                         int u0, int u1, float& a0, float& a1)
{
    for (int i = 0; i < n; i += 8) {
        float w0[8], w1[8];
#pragma unroll
        for (int k = 0; k < 8; k++) {
            size_t r = (size_t)list[i + k] * 512;
            w0[k] = W[r + u0];
            w1[k] = W[r + u1];
        }
#pragma unroll
        for (int k = 0; k < 8; k++) {
            if (i + k < n) { a0 += w0[k]; a1 += w1[k]; }
        }
    }
}

__device__ __forceinline__ void gather8d_2(const float* __restrict__ Win,
                                           const float* __restrict__ Wrec,
                                           const unsigned short* list, int n,
                                           int u0, int u1, float& a0, float& a1)
{
    for (int i = 0; i < n; i += 8) {
        float w0[8], w1[8];
#pragma unroll
        for (int k = 0; k < 8; k++) {
            int j = list[i + k];
            const float* base = (j < 1024) ? (Win + (size_t)j * 512)
                                           : (Wrec + (size_t)(j - 1024) * 512);
            w0[k] = base[u0];
            w1[k] = base[u1];
        }
#pragma unroll
        for (int k = 0; k < 8; k++) {
            if (i + k < n) { a0 += w0[k]; a1 += w1[k]; }
        }
    }
}

// ---------------------------------------------------------------------------
// GEMM role: 256 threads, 128x128 tile, 8x8 f32x2/thread, 2-stage cp.async.
// ---------------------------------------------------------------------------
__device__ void gemm_role(int g,
                          const float* __restrict__ Wk,
                          const float* __restrict__ Wq,
                          const float* __restrict__ Wv,
                          GemmSmem* gs)
{
    const int mchunk = g / 12;
    const int rem    = g % 12;
    const int pop    = rem >> 2;
    const int nt     = rem & 3;
    const float* __restrict__ W = (pop == 0) ? Wk : (pop == 1) ? Wq : Wv;
    float* __restrict__ C = g_I + (size_t)pop * MTOT * NU;

    const int tid = threadIdx.x;
    const int r0 = mchunk * 128;
    const int n0 = nt * 128;
    const int tx = tid & 15;
    const int ty = tid >> 4;
    const int noff = (tx & 3) * 32 + (tx >> 2) * 8;

    const float* srcA[2];
    const float* srcB[2];
    unsigned dstA[2][2], dstB[2][2];
#pragma unroll
    for (int l = 0; l < 2; l++) {
        int idx = l * 256 + tid;
        int kr = idx >> 5, sg = idx & 31;
        srcA[l] = g_xT + (size_t)kr * MTOT + r0 + sg * 4;
        srcB[l] = W + (size_t)kr * 512 + n0 + sg * 4;
#pragma unroll
        for (int s = 0; s < 2; s++) {
            dstA[s][l] = smem_u32(&gs->As[s][kr][sg * 4]);
            dstB[s][l] = smem_u32(&gs->Bs[s][kr][sg * 4]);
        }
    }

    unsigned long long acc[8][4];
#pragma unroll
    for (int i = 0; i < 8; i++)
#pragma unroll
        for (int j = 0; j < 4; j++) acc[i][j] = 0ull;

#pragma unroll
    for (int l = 0; l < 2; l++) {
        CP_ASYNC16(dstA[0][l], srcA[l]);
        CP_ASYNC16(dstB[0][l], srcB[l]);
    }
    CP_COMMIT();

    for (int kt = 0; kt < 32; kt++) {
        if (kt < 31) {
            const int k0 = (kt + 1) * 16;
            const int s = (kt + 1) & 1;
#pragma unroll
            for (int l = 0; l < 2; l++) {
                CP_ASYNC16(dstA[s][l], srcA[l] + (size_t)k0 * MTOT);
                CP_ASYNC16(dstB[s][l], srcB[l] + (size_t)k0 * 512);
            }
            CP_COMMIT();
            CP_WAIT(1);
        } else {
            CP_WAIT(0);
        }
        __syncthreads();

        const int s = kt & 1;
#pragma unroll
        for (int kk = 0; kk < 16; kk++) {
            float4 a0 = *(const float4*)&gs->As[s][kk][ty * 8];
            float4 a1 = *(const float4*)&gs->As[s][kk][ty * 8 + 4];
            ulonglong2 b01 = *(const ulonglong2*)&gs->Bs[s][kk][noff];
            ulonglong2 b23 = *(const ulonglong2*)&gs->Bs[s][kk][noff + 4];
            unsigned long long bp0 = b01.x, bp1 = b01.y, bp2 = b23.x, bp3 = b23.y;
            float av[8] = {a0.x, a0.y, a0.z, a0.w, a1.x, a1.y, a1.z, a1.w};
#pragma unroll
            for (int i = 0; i < 8; i++) {
                unsigned long long ad;
                PACK_DUP2(ad, av[i]);
                FMA_F32X2(acc[i][0], ad, bp0);
                FMA_F32X2(acc[i][1], ad, bp1);
                FMA_F32X2(acc[i][2], ad, bp2);
                FMA_F32X2(acc[i][3], ad, bp3);
            }
        }
        __syncthreads();
    }

#pragma unroll
    for (int i = 0; i < 8; i++) {
        float* Crow = C + (size_t)(r0 + ty * 8 + i) * 512 + n0 + noff;
        ulonglong2 v0; v0.x = acc[i][0]; v0.y = acc[i][1];
        ulonglong2 v1; v1.x = acc[i][2]; v1.y = acc[i][3];
        *(ulonglong2*)Crow = v0;
        *((ulonglong2*)Crow + 1) = v1;
    }
    __syncthreads();
    if (tid == 0) red_release_add(&g_chunk[mchunk], 1);   // drains C stores (needed)
}

// ---------------------------------------------------------------------------
// lsnn role: ONE population, one batch. 256 threads, 2 neurons/thread.
// 2 bars/step. I register-prefetched; chunk poll folded into B1.
// ---------------------------------------------------------------------------
__device__ void lsnn_role(int p, int b, const float* __restrict__ Wr,
                          float* __restrict__ d_out, ScanSmem* ss)
{
    const float* __restrict__ I = g_I + (size_t)p * MTOT * NU;
    unsigned long long* __restrict__ spk = g_spk64 + ((size_t)p * NB + b) * NT * 16;

    float* __restrict__ out2 = d_out + OUT2_OFF;
    float* __restrict__ out3 = d_out + OUT3_OFF;
    float* __restrict__ out4 = d_out + OUT4_OFF;

    const int tid = threadIdx.x, warp = tid >> 5, lane = tid & 31;
    const int u0 = tid, u1 = tid + 256;

    if (tid < 16) ss->mask[tid] = 0u;
    __syncthreads();

    float v0 = 0.f, a0 = 0.f, z0 = 0.f;
    float v1 = 0.f, a1 = 0.f, z1 = 0.f;
    float pre0 = 0.f, pre1 = 0.f;

    for (int t = 0; t < NT; t++) {
        if ((t & 3) == 0 && tid == 0) spin_ge(&g_chunk[t >> 2], 12);

        if (warp == 0) {
            int tot = build_list(lane < 16 ? ss->mask[lane] : 0u, 0, ss->list, 0);
            if (lane < 8) ss->list[tot + lane] = 0;
            if (lane == 0) ss->tot = tot;
        }
        __syncthreads();                                    // B1 (orders poll + list)

        float I0, I1;
        if ((t & 3) == 0) {
            const size_t io = ((size_t)t * 32 + b) * 512;
            I0 = I[io + u0]; I1 = I[io + u1];
        } else {
            I0 = pre0; I1 = pre1;
        }
        if (t + 1 < NT && ((t + 1) & 3) != 0) {
            const size_t io = ((size_t)(t + 1) * 32 + b) * 512;
            pre0 = I[io + u0]; pre1 = I[io + u1];
        }

        const int n = ss->tot;
        float acc0 = I0, acc1 = I1;
        gather8d(Wr, ss->list, n, u0, u1, acc0, acc1);

        float a0n = RHO * a0 + z0, thr0 = 1.0f + BETA * a0n;
        float v0n = ALPHA * v0 + acc0 - z0 * thr0, vsc0 = v0n - thr0;
        float z0n = (vsc0 > 0.f) ? 1.f : 0.f;
        float a1n = RHO * a1 + z1, thr1 = 1.0f + BETA * a1n;
        float v1n = ALPHA * v1 + acc1 - z1 * thr1, vsc1 = v1n - thr1;
        float z1n = (vsc1 > 0.f) ? 1.f : 0.f;

        unsigned bal0 = __ballot_sync(0xffffffffu, z0n > 0.f);
        unsigned bal1 = __ballot_sync(0xffffffffu, z1n > 0.f);
        if (lane == 0) {
            ss->mask[warp]     = bal0;
            ss->mask[8 + warp] = bal1;
            const unsigned seq = (unsigned)(t + 1);
            push_word(&spk[(size_t)t * 16 + warp],     seq, bal0);
            push_word(&spk[(size_t)t * 16 + 8 + warp], seq, bal1);
        }
        __syncthreads();                                    // B2 (mask ready for t+1)

        const size_t base = (size_t)b * NT + t;
        __stcs(&out2[base * 3072 + (size_t)p * 512 + u0], z0n);
        __stcs(&out2[base * 3072 + (size_t)p * 512 + u1], z1n);
        __stcs(&out3[base * 2048 + (size_t)p * 512 + u0], thr0);
        __stcs(&out3[base * 2048 + (size_t)p * 512 + u1], thr1);
        __stcs(&out4[base * 3072 + (size_t)p * 512 + u0], vsc0);
        __stcs(&out4[base * 3072 + (size_t)p * 512 + u1], vsc1);

        v0 = v0n; a0 = a0n; z0 = z0n;
        v1 = v1n; a1 = a1n; z1 = z1n;
    }
}

// ---------------------------------------------------------------------------
// WTA role: 256 threads, 2 neurons/thread. 3 bars/step (end barrier removed;
// B1/B2 of step t+1 order all smem reuse).
// ---------------------------------------------------------------------------
__device__ void wta_role(int b, const float* __restrict__ Wa,
                         const float* __restrict__ Wb,
                         float* __restrict__ d_out, ScanSmem* ss)
{
    const unsigned long long* __restrict__ spkK = g_spk64 + (size_t)b * NT * 16;
    const unsigned long long* __restrict__ spkQ = g_spk64 + ((size_t)NB + b) * NT * 16;
    unsigned long long* __restrict__ zAout      = g_zA64 + (size_t)b * NT * 16;

    float* __restrict__ out2 = d_out + OUT2_OFF;
    float* __restrict__ out4 = d_out + OUT4_OFF;

    const int tid = threadIdx.x, warp = tid >> 5, lane = tid & 31;
    const int u0 = tid, u1 = tid + 256;

    float vA0 = 0.f, vB0 = 0.f, zA0 = 0.f, zB0 = 0.f;
    float vA1 = 0.f, vB1 = 0.f, zA1 = 0.f, zB1 = 0.f;

    for (int t = 0; t < NT; t++) {
        if (warp == 0) {
            const unsigned seq = (unsigned)(t + 1);
            unsigned m = (lane < 16) ? poll_word(&spkK[(size_t)t * 16 + lane], seq)
                                     : poll_word(&spkQ[(size_t)t * 16 + (lane - 16)], seq);
            int tot = build_list(m, 0, ss->list, 0);
            if (lane < 8) ss->list[tot + lane] = 0;
            if (lane == 0) ss->tot = tot;
        }
        __syncthreads();                                   // B1
        const int nsp = ss->tot;

        float acc0 = 0.f, acc1 = 0.f;
        gather8d(Wa, ss->list, nsp, u0, u1, acc0, acc1);

        float vA0n = ALPHA * vA0 + acc0 - zA0;
        float vA1n = ALPHA * vA1 + acc1 - zA1;
        float vscA0 = vA0n - 1.0f, vscA1 = vA1n - 1.0f;

        float mx = fmaxf(vA0n, vA1n);
#pragma unroll
        for (int o = 16; o > 0; o >>= 1) mx = fmaxf(mx, __shfl_xor_sync(0xffffffffu, mx, o));
        if (lane == 0) ss->red[warp] = mx;
        __syncthreads();                                   // B2
        float mm = ss->red[lane & 7];
#pragma unroll
        for (int o = 4; o > 0; o >>= 1) mm = fmaxf(mm, __shfl_xor_sync(0xffffffffu, mm, o));

        float zA0n = (vscA0 > 0.f && vA0n == mm) ? 1.f : 0.f;
        float zA1n = (vscA1 > 0.f && vA1n == mm) ? 1.f : 0.f;

        unsigned balZ0 = __ballot_sync(0xffffffffu, zA0n > 0.f);
        unsigned balZ1 = __ballot_sync(0xffffffffu, zA1n > 0.f);
        if (lane == 0) {
            ss->maskZ[warp]     = balZ0;
            ss->maskZ[8 + warp] = balZ1;
            const unsigned seq = (unsigned)(t + 1);
            push_word(&zAout[(size_t)t * 16 + warp],     seq, balZ0);
            push_word(&zAout[(size_t)t * 16 + 8 + warp], seq, balZ1);
        }
        __syncthreads();                                   // B3

        float accB0 = 0.f, accB1 = 0.f;
#pragma unroll
        for (int w = 0; w < 16; w++) {
            unsigned mb = ss->maskZ[w];
            while (mb) {
                int j = __ffs((int)mb) - 1;
                size_t r = (size_t)(w * 32 + j) * 512;
                accB0 += Wb[r + u0];
                accB1 += Wb[r + u1];
                mb &= mb - 1;
            }
        }
        float vB0n = ALPHA * vB0 + accB0 - zB0, vscB0 = vB0n - 1.0f;
        float zB0n = (vscB0 > 0.f) ? 1.f : 0.f;
        float vB1n = ALPHA * vB1 + accB1 - zB1, vscB1 = vB1n - 1.0f;
        float zB1n = (vscB1 > 0.f) ? 1.f : 0.f;

        const size_t base = (size_t)b * NT + t;
        __stcs(&out2[base * 3072 + 3 * 512 + u0], zA0n);  __stcs(&out2[base * 3072 + 3 * 512 + u1], zA1n);
        __stcs(&out2[base * 3072 + 4 * 512 + u0], zB0n);  __stcs(&out2[base * 3072 + 4 * 512 + u1], zB1n);
        __stcs(&out4[base * 3072 + 3 * 512 + u0], vscA0); __stcs(&out4[base * 3072 + 3 * 512 + u1], vscA1);
        __stcs(&out4[base * 3072 + 4 * 512 + u0], vscB0); __stcs(&out4[base * 3072 + 4 * 512 + u1], vscB1);

        vA0 = vA0n; vB0 = vB0n; zA0 = zA0n; zB0 = zB0n;
        vA1 = vA1n; vB1 = vB1n; zA1 = zA1n; zB1 = zB1n;
        // no end barrier: B1(t+1)/B2(t+1) order all smem reuse
    }
}

// ---------------------------------------------------------------------------
// Attention LSNN role: 256 threads, 2 neurons/thread. 2 bars/step.
// ---------------------------------------------------------------------------
__device__ void att_role(int b, const float* __restrict__ Win,
                         const float* __restrict__ Wrec,
                         float* __restrict__ d_out, ScanSmem* ss)
{
    const unsigned long long* __restrict__ spkV = g_spk64 + ((size_t)2 * NB + b) * NT * 16;
    const unsigned long long* __restrict__ zAin = g_zA64 + (size_t)b * NT * 16;

    float* __restrict__ out1 = d_out + OUT1_OFF;
    float* __restrict__ out2 = d_out + OUT2_OFF;
    float* __restrict__ out3 = d_out + OUT3_OFF;
    float* __restrict__ out4 = d_out + OUT4_OFF;

    const int tid = threadIdx.x, warp = tid >> 5, lane = tid & 31;
    const int u0 = tid, u1 = tid + 256;

    if (tid < 16) ss->maskR[tid] = 0u;
    __syncthreads();

    float v0 = 0.f, a0 = 0.f, z0 = 0.f;
    float v1 = 0.f, a1 = 0.f, z1 = 0.f;

    for (int t = 0; t < NT; t++) {
        if (warp == 0) {
            const unsigned seq = (unsigned)(t + 1);
            unsigned m1 = (lane < 16) ? poll_word(&spkV[(size_t)t * 16 + lane], seq)
                                      : poll_word(&zAin[(size_t)t * 16 + (lane - 16)], seq);
            int t1 = build_list(m1, 0, ss->list, 0);
            unsigned m2 = (lane < 16) ? ss->maskR[lane] : 0u;
            int t2 = build_list(m2, 1024, ss->list, t1);
            int tot = t1 + t2;
            if (lane < 8) ss->list[tot + lane] = 0;
            if (lane == 0) ss->tot = tot;
        }
        __syncthreads();                                   // B1
        const int nsp = ss->tot;

        float acc0 = 0.f, acc1 = 0.f;
        gather8d_2(Win, Wrec, ss->list, nsp, u0, u1, acc0, acc1);

        float a0n = RHO * a0 + z0, thr0 = 1.0f + BETA * a0n;
        float v0n = ALPHA * v0 + acc0 - z0 * thr0, vsc0 = v0n - thr0;
        float z0n = (vsc0 > 0.f) ? 1.f : 0.f;
        float a1n = RHO * a1 + z1, thr1 = 1.0f + BETA * a1n;
        float v1n = ALPHA * v1 + acc1 - z1 * thr1, vsc1 = v1n - thr1;
        float z1n = (vsc1 > 0.f) ? 1.f : 0.f;

        unsigned bal0 = __ballot_sync(0xffffffffu, z0n > 0.f);
        unsigned bal1 = __ballot_sync(0xffffffffu, z1n > 0.f);
        if (lane == 0) {
            ss->maskR[warp]     = bal0;
            ss->maskR[8 + warp] = bal1;
        }

        const size_t base = (size_t)b * NT + t;
        __stcs(&out1[base * 512 + u0], z0n);             __stcs(&out1[base * 512 + u1], z1n);
        __stcs(&out2[base * 3072 + 5 * 512 + u0], z0n);  __stcs(&out2[base * 3072 + 5 * 512 + u1], z1n);
        __stcs(&out3[base * 2048 + 3 * 512 + u0], thr0); __stcs(&out3[base * 2048 + 3 * 512 + u1], thr1);
        __stcs(&out4[base * 3072 + 5 * 512 + u0], vsc0); __stcs(&out4[base * 3072 + 5 * 512 + u1], vsc1);

        v0 = v0n; a0 = a0n; z0 = z0n;
        v1 = v1n; a1 = a1n; z1 = z1n;
        __syncthreads();                                   // B2 (protects maskR)
    }
}

// ---------------------------------------------------------------------------
__global__ __launch_bounds__(256, 2) void fused_kernel(
    const float* __restrict__ Wk_in, const float* __restrict__ Wk_rec,
    const float* __restrict__ Wq_in, const float* __restrict__ Wq_rec,
    const float* __restrict__ Wv_in, const float* __restrict__ Wv_rec,
    const float* __restrict__ Watt_in, const float* __restrict__ Watt_rec,
    const float* __restrict__ Wwta_a, const float* __restrict__ Wwta_b,
    float* __restrict__ d_out)
{
    __shared__ __align__(16) unsigned char smem_raw[
        sizeof(GemmSmem) > sizeof(ScanSmem) ? sizeof(GemmSmem) : sizeof(ScanSmem)];
    const int bid = blockIdx.x;

    if (bid >= 160) {
        gemm_role(bid - 160, Wk_in, Wq_in, Wv_in, (GemmSmem*)smem_raw);
        return;
    }
    ScanSmem* ss = (ScanSmem*)smem_raw;
    if (bid < 96) {
        const int p = bid >> 5, b = bid & 31;
        const float* Wr = (p == 0) ? Wk_rec : (p == 1) ? Wq_rec : Wv_rec;
        lsnn_role(p, b, Wr, d_out, ss);
    } else if (bid < 128) {
        wta_role(bid - 96, Wwta_a, Wwta_b, d_out, ss);
    } else {
        att_role(bid - 128, Watt_in, Watt_rec, d_out, ss);
    }
}

// ---------------------------------------------------------------------------
extern "C" void kernel_launch(void* const* d_in, const int* in_sizes, int n_in,
                              void* d_out, int out_size)
{
    const float* x        = (const float*)d_in[0];
    const float* Wk_in    = (const float*)d_in[1];
    const float* Wk_rec   = (const float*)d_in[2];
    const float* Wq_in    = (const float*)d_in[3];
    const float* Wq_rec   = (const float*)d_in[4];
    const float* Wv_in    = (const float*)d_in[5];
    const float* Wv_rec   = (const float*)d_in[6];
    const float* Watt_in  = (const float*)d_in[7];
    const float* Watt_rec = (const float*)d_in[8];
    const float* Wwta_a   = (const float*)d_in[9];
    const float* Wwta_b   = (const float*)d_in[10];
    float* out = (float*)d_out;

    (void)in_sizes; (void)n_in; (void)out_size;

    dim3 gT(1000, 4);
    transpose_kernel<<<gT, 256>>>(x);
    reset_kernel<<<512, 512>>>();
    fused_kernel<<<160 + 3000, 256>>>(Wk_in, Wk_rec, Wq_in, Wq_rec,
                                      Wv_in, Wv_rec, Watt_in, Watt_rec,
                                      Wwta_a, Wwta_b, out);
}

// round 16
// speedup vs baseline: 1.0942x; 1.0942x over previous
#include <cuda_runtime.h>
#include <cstdint>

// ---------------------------------------------------------------------------
// SpikingAttention: adaptive-LIF (LSNN) scans + WTA pseudo-softmax
// B=32, T=1000, D=512, U=512
// Single fused kernel, 256-thread blocks (R14 architecture + micro-trims):
//   Blocks 0..31  : kqv role (k,q,v lsnn, 2 neurons/thread)
//   Blocks 32..63 : wta role
//   Blocks 64..95 : att role
//   Blocks 96..3095: GEMM tiles (8x8 f32x2/thread)
// Handoffs: self-validating 64-bit words (seq<<32|mask) via st/ld.relaxed.gpu.
// Trims vs R14: kqv I register-prefetch (no cp.async Ibuf, -2 bars/4 steps),
// kqv 8-wide gathers, wta end-barrier removed.
// ---------------------------------------------------------------------------

#define ALPHA 0.9f
#define RHO   0.995f
#define BETA  1.6f

#define NB 32
#define NT 1000
#define NU 512
#define MTOT (NB*NT)

#define OUT1_OFF 0ull
#define OUT2_OFF 16384000ull
#define OUT3_OFF 114688000ull
#define OUT4_OFF 180224000ull

__device__ float              g_xT[512ll * MTOT];        // x transposed: [k][t*32+b]
__device__ float              g_I[3ll * MTOT * NU];      // [pop][t*32+b][u]
__device__ unsigned long long g_spk64[3ll * MTOT * 16];  // [pop][b][t][16]: seq<<32|mask
__device__ unsigned long long g_zA64[(long long)MTOT * 16];
__device__ int                g_chunk[250];              // GEMM chunk completion (12)

// ---------------------------------------------------------------------------
__device__ __forceinline__ int ld_acquire(const int* p) {
    int v;
    asm volatile("ld.acquire.gpu.global.s32 %0, [%1];" : "=r"(v) : "l"(p) : "memory");
    return v;
}
__device__ __forceinline__ void red_release_add(int* p, int v) {
    asm volatile("red.release.gpu.global.add.s32 [%0], %1;" :: "l"(p), "r"(v) : "memory");
}
__device__ __forceinline__ void spin_ge(const int* p, int want) {
    while (ld_acquire(p) < want) { }
}

// self-validating mask word: high 32 = seq (t+1), low 32 = mask
__device__ __forceinline__ void push_word(unsigned long long* p, unsigned seq, unsigned mask) {
    unsigned long long v = ((unsigned long long)seq << 32) | (unsigned long long)mask;
    asm volatile("st.relaxed.gpu.global.u64 [%0], %1;" :: "l"(p), "l"(v) : "memory");
}
__device__ __forceinline__ unsigned poll_word(const unsigned long long* p, unsigned seq) {
    unsigned long long v;
    do {
        asm volatile("ld.relaxed.gpu.global.u64 %0, [%1];" : "=l"(v) : "l"(p) : "memory");
    } while ((unsigned)(v >> 32) != seq);
    return (unsigned)v;
}

#define FMA_F32X2(acc, a, b) \
    asm("fma.rn.f32x2 %0, %1, %2, %0;" : "+l"(acc) : "l"(a), "l"(b))
#define PACK_DUP2(out, f) \
    asm("mov.b64 %0, {%1, %1};" : "=l"(out) : "f"(f))

#define CP_ASYNC16(smem_addr, gptr) \
    asm volatile("cp.async.cg.shared.global [%0], [%1], 16;" :: "r"(smem_addr), "l"(gptr))
#define CP_COMMIT()  asm volatile("cp.async.commit_group;")
#define CP_WAIT(N)   asm volatile("cp.async.wait_group %0;" :: "n"(N))

__device__ __forceinline__ unsigned smem_u32(const void* p) {
    return (unsigned)__cvta_generic_to_shared(p);
}

// ---------------------------------------------------------------------------
// Transpose: x[b][t][k] -> xT[k][t*32+b]. grid (1000, 4), 256 threads.
// ---------------------------------------------------------------------------
__global__ __launch_bounds__(256) void transpose_kernel(const float* __restrict__ x)
{
    __shared__ float S[32][132];
    const int t  = blockIdx.x;
    const int kc = blockIdx.y;
    const int tid = threadIdx.x;
#pragma unroll
    for (int i = 0; i < 4; i++) {
        int f = i * 256 + tid;
        int b = f >> 5;
        int c4 = f & 31;
        float4 v = *(const float4*)(x + ((size_t)b * 1000 + t) * 512 + kc * 128 + c4 * 4);
        *(float4*)&S[b][c4 * 4] = v;
    }
    __syncthreads();
#pragma unroll
    for (int i = 0; i < 4; i++) {
        int f = i * 256 + tid;
        int kk = f >> 3;
        int c = f & 7;
        float4 v = make_float4(S[c * 4 + 0][kk], S[c * 4 + 1][kk],
                               S[c * 4 + 2][kk], S[c * 4 + 3][kk]);
        *(float4*)(g_xT + (size_t)(kc * 128 + kk) * MTOT + t * 32 + c * 4) = v;
    }
}

// reset: zero seq fields + chunk counters (stale seqs across graph replays).
__global__ void reset_kernel()
{
    const long long N1 = 3ll * MTOT * 16;
    const long long N2 = (long long)MTOT * 16;
    long long gid = (long long)blockIdx.x * blockDim.x + threadIdx.x;
    long long stride = (long long)gridDim.x * blockDim.x;
    for (long long i = gid; i < N1; i += stride) g_spk64[i] = 0ull;
    for (long long i = gid; i < N2; i += stride) g_zA64[i] = 0ull;
    if (gid < 250) g_chunk[gid] = 0;
}

// ---------------------------------------------------------------------------
struct GemmSmem {
    float As[2][16][128];
    float Bs[2][16][128];
};
struct ScanSmem {
    unsigned mask[3][16];
    unsigned maskZ[16];
    unsigned maskR[16];
    float red[8];
    int totK, totQ, totV, totKQ, totAtt;
    unsigned short listK[528], listQ[528], listV[528];
    unsigned short listKQ[1056];
    unsigned short listAtt[1584];
};

// ---------------------------------------------------------------------------
__device__ __forceinline__ int build_list(unsigned m, int bias,
                                          unsigned short* list, int list_off)
{
    const int lane = threadIdx.x & 31;
    int c = __popc(m);
    int inc = c;
#pragma unroll
    for (int o = 1; o < 32; o <<= 1) {
        int v = __shfl_up_sync(0xffffffffu, inc, o);
        if (lane >= o) inc += v;
    }
    int off  = list_off + inc - c;
    int base = bias + lane * 32;
    while (m) {
        int j = __ffs((int)m) - 1;
        list[off++] = (unsigned short)(base + j);
        m &= (m - 1);
    }
    return __shfl_sync(0xffffffffu, inc, 31);
}

// 8-wide batched dual-neuron gather (list padded with >=8 zeros past n)
__device__ __forceinline__ void gather8d(const float* __restrict__ W,
                                         const unsigned short* list, int n,
                                         int u0, int u1, float& a0, float& a1)
{
    for (int i = 0; i < n; i += 8) {
        float w0[8], w1[8];
#pragma unroll
        for (int k = 0; k < 8; k++) {
            size_t r = (size_t)list[i + k] * 512;
            w0[k] = W[r + u0];
            w1[k] = W[r + u1];
        }
#pragma unroll
        for (int k = 0; k < 8; k++) {
            if (i + k < n) { a0 += w0[k]; a1 += w1[k]; }
        }
    }
}

__device__ __forceinline__ void gather8d_2(const float* __restrict__ Win,
                                           const float* __restrict__ Wrec,
                                           const unsigned short* list, int n,
                                           int u0, int u1, float& a0, float& a1)
{
    for (int i = 0; i < n; i += 8) {
        float w0[8], w1[8];
#pragma unroll
        for (int k = 0; k < 8; k++) {
            int j = list[i + k];
            const float* base = (j < 1024) ? (Win + (size_t)j * 512)
                                           : (Wrec + (size_t)(j - 1024) * 512);
            w0[k] = base[u0];
            w1[k] = base[u1];
        }
#pragma unroll
        for (int k = 0; k < 8; k++) {
            if (i + k < n) { a0 += w0[k]; a1 += w1[k]; }
        }
    }
}

// ---------------------------------------------------------------------------
// GEMM role: 256 threads, 128x128 tile, 8x8 f32x2/thread, 2-stage cp.async.
// ---------------------------------------------------------------------------
__device__ void gemm_role(int g,
                          const float* __restrict__ Wk,
                          const float* __restrict__ Wq,
                          const float* __restrict__ Wv,
                          GemmSmem* gs)
{
    const int mchunk = g / 12;
    const int rem    = g % 12;
    const int pop    = rem >> 2;
    const int nt     = rem & 3;
    const float* __restrict__ W = (pop == 0) ? Wk : (pop == 1) ? Wq : Wv;
    float* __restrict__ C = g_I + (size_t)pop * MTOT * NU;

    const int tid = threadIdx.x;
    const int r0 = mchunk * 128;
    const int n0 = nt * 128;
    const int tx = tid & 15;
    const int ty = tid >> 4;
    const int noff = (tx & 3) * 32 + (tx >> 2) * 8;

    const float* srcA[2];
    const float* srcB[2];
    unsigned dstA[2][2], dstB[2][2];
#pragma unroll
    for (int l = 0; l < 2; l++) {
        int idx = l * 256 + tid;
        int kr = idx >> 5, sg = idx & 31;
        srcA[l] = g_xT + (size_t)kr * MTOT + r0 + sg * 4;
        srcB[l] = W + (size_t)kr * 512 + n0 + sg * 4;
#pragma unroll
        for (int s = 0; s < 2; s++) {
            dstA[s][l] = smem_u32(&gs->As[s][kr][sg * 4]);
            dstB[s][l] = smem_u32(&gs->Bs[s][kr][sg * 4]);
        }
    }

    unsigned long long acc[8][4];
#pragma unroll
    for (int i = 0; i < 8; i++)
#pragma unroll
        for (int j = 0; j < 4; j++) acc[i][j] = 0ull;

#pragma unroll
    for (int l = 0; l < 2; l++) {
        CP_ASYNC16(dstA[0][l], srcA[l]);
        CP_ASYNC16(dstB[0][l], srcB[l]);
    }
    CP_COMMIT();

    for (int kt = 0; kt < 32; kt++) {
        if (kt < 31) {
            const int k0 = (kt + 1) * 16;
            const int s = (kt + 1) & 1;
#pragma unroll
            for (int l = 0; l < 2; l++) {
                CP_ASYNC16(dstA[s][l], srcA[l] + (size_t)k0 * MTOT);
                CP_ASYNC16(dstB[s][l], srcB[l] + (size_t)k0 * 512);
            }
            CP_COMMIT();
            CP_WAIT(1);
        } else {
            CP_WAIT(0);
        }
        __syncthreads();

        const int s = kt & 1;
#pragma unroll
        for (int kk = 0; kk < 16; kk++) {
            float4 a0 = *(const float4*)&gs->As[s][kk][ty * 8];
            float4 a1 = *(const float4*)&gs->As[s][kk][ty * 8 + 4];
            ulonglong2 b01 = *(const ulonglong2*)&gs->Bs[s][kk][noff];
            ulonglong2 b23 = *(const ulonglong2*)&gs->Bs[s][kk][noff + 4];
            unsigned long long bp0 = b01.x, bp1 = b01.y, bp2 = b23.x, bp3 = b23.y;
            float av[8] = {a0.x, a0.y, a0.z, a0.w, a1.x, a1.y, a1.z, a1.w};
#pragma unroll
            for (int i = 0; i < 8; i++) {
                unsigned long long ad;
                PACK_DUP2(ad, av[i]);
                FMA_F32X2(acc[i][0], ad, bp0);
                FMA_F32X2(acc[i][1], ad, bp1);
                FMA_F32X2(acc[i][2], ad, bp2);
                FMA_F32X2(acc[i][3], ad, bp3);
            }
        }
        __syncthreads();
    }

#pragma unroll
    for (int i = 0; i < 8; i++) {
        float* Crow = C + (size_t)(r0 + ty * 8 + i) * 512 + n0 + noff;
        ulonglong2 v0; v0.x = acc[i][0]; v0.y = acc[i][1];
        ulonglong2 v1; v1.x = acc[i][2]; v1.y = acc[i][3];
        *(ulonglong2*)Crow = v0;
        *((ulonglong2*)Crow + 1) = v1;
    }
    __syncthreads();
    if (tid == 0) red_release_add(&g_chunk[mchunk], 1);
}

// ---------------------------------------------------------------------------
// kqv role: 256 threads, 2 neurons/thread (u, u+256). 2 bars/step.
// I register-prefetched (chunk-boundary steps load directly after the gate).
// ---------------------------------------------------------------------------
__device__ void kqv_role(int b,
                         const float* __restrict__ WkR,
                         const float* __restrict__ WqR,
                         const float* __restrict__ WvR,
                         float* __restrict__ d_out, ScanSmem* ss)
{
    const float* __restrict__ Ik = g_I + (size_t)0 * MTOT * NU;
    const float* __restrict__ Iq = g_I + (size_t)1 * MTOT * NU;
    const float* __restrict__ Iv = g_I + (size_t)2 * MTOT * NU;

    unsigned long long* __restrict__ spkK = g_spk64 + ((size_t)0 * NB + b) * NT * 16;
    unsigned long long* __restrict__ spkQ = g_spk64 + ((size_t)1 * NB + b) * NT * 16;
    unsigned long long* __restrict__ spkV = g_spk64 + ((size_t)2 * NB + b) * NT * 16;

    float* __restrict__ out2 = d_out + OUT2_OFF;
    float* __restrict__ out3 = d_out + OUT3_OFF;
    float* __restrict__ out4 = d_out + OUT4_OFF;

    const int tid = threadIdx.x, warp = tid >> 5, lane = tid & 31;
    const int u0 = tid, u1 = tid + 256;

    if (tid < 48) ((unsigned*)ss->mask)[tid] = 0u;
    __syncthreads();

    float vK0 = 0.f, aK0 = 0.f, zK0 = 0.f, vK1 = 0.f, aK1 = 0.f, zK1 = 0.f;
    float vQ0 = 0.f, aQ0 = 0.f, zQ0 = 0.f, vQ1 = 0.f, aQ1 = 0.f, zQ1 = 0.f;
    float vV0 = 0.f, aV0 = 0.f, zV0 = 0.f, vV1 = 0.f, aV1 = 0.f, zV1 = 0.f;
    float pK0 = 0.f, pK1 = 0.f, pQ0 = 0.f, pQ1 = 0.f, pV0 = 0.f, pV1 = 0.f;

    for (int t = 0; t < NT; t++) {
        if ((t & 3) == 0 && tid == 0) spin_ge(&g_chunk[t >> 2], 12);

        if (warp == 0) {
            int tot = build_list(lane < 16 ? ss->mask[0][lane] : 0u, 0, ss->listK, 0);
            if (lane < 8) ss->listK[tot + lane] = 0;
            if (lane == 0) ss->totK = tot;
        } else if (warp == 1) {
            int tot = build_list(lane < 16 ? ss->mask[1][lane] : 0u, 0, ss->listQ, 0);
            if (lane < 8) ss->listQ[tot + lane] = 0;
            if (lane == 0) ss->totQ = tot;
        } else if (warp == 2) {
            int tot = build_list(lane < 16 ? ss->mask[2][lane] : 0u, 0, ss->listV, 0);
            if (lane < 8) ss->listV[tot + lane] = 0;
            if (lane == 0) ss->totV = tot;
        }
        __syncthreads();                                    // B1 (orders gate + lists)

        // I for this step (direct at chunk boundary, prefetched otherwise)
        float IK0, IK1, IQ0, IQ1, IV0, IV1;
        if ((t & 3) == 0) {
            const size_t io = ((size_t)t * 32 + b) * 512;
            IK0 = Ik[io + u0]; IK1 = Ik[io + u1];
            IQ0 = Iq[io + u0]; IQ1 = Iq[io + u1];
            IV0 = Iv[io + u0]; IV1 = Iv[io + u1];
        } else {
            IK0 = pK0; IK1 = pK1; IQ0 = pQ0; IQ1 = pQ1; IV0 = pV0; IV1 = pV1;
        }
        // prefetch next step's I if within the same (gated) chunk
        if (t + 1 < NT && ((t + 1) & 3) != 0) {
            const size_t io = ((size_t)(t + 1) * 32 + b) * 512;
            pK0 = Ik[io + u0]; pK1 = Ik[io + u1];
            pQ0 = Iq[io + u0]; pQ1 = Iq[io + u1];
            pV0 = Iv[io + u0]; pV1 = Iv[io + u1];
        }

        const int nK = ss->totK, nQ = ss->totQ, nV = ss->totV;
        float accK0 = IK0, accK1 = IK1;
        float accQ0 = IQ0, accQ1 = IQ1;
        float accV0 = IV0, accV1 = IV1;
        {
            int nmax = nK > nQ ? nK : nQ;
            if (nV > nmax) nmax = nV;
            for (int i = 0; i < nmax; i += 8) {
                float wk0[8], wk1[8], wq0[8], wq1[8], wv0[8], wv1[8];
                const bool dk = i < nK, dq = i < nQ, dv = i < nV;
#pragma unroll
                for (int k2 = 0; k2 < 8; k2++) {
                    if (dk) { size_t r = (size_t)ss->listK[i + k2] * 512; wk0[k2] = WkR[r + u0]; wk1[k2] = WkR[r + u1]; }
                    if (dq) { size_t r = (size_t)ss->listQ[i + k2] * 512; wq0[k2] = WqR[r + u0]; wq1[k2] = WqR[r + u1]; }
                    if (dv) { size_t r = (size_t)ss->listV[i + k2] * 512; wv0[k2] = WvR[r + u0]; wv1[k2] = WvR[r + u1]; }
                }
#pragma unroll
                for (int k2 = 0; k2 < 8; k2++) {
                    if (i + k2 < nK) { accK0 += wk0[k2]; accK1 += wk1[k2]; }
                    if (i + k2 < nQ) { accQ0 += wq0[k2]; accQ1 += wq1[k2]; }
                    if (i + k2 < nV) { accV0 += wv0[k2]; accV1 += wv1[k2]; }
                }
            }
        }

        float aK0n = RHO * aK0 + zK0, thrK0 = 1.0f + BETA * aK0n;
        float vK0n = ALPHA * vK0 + accK0 - zK0 * thrK0, vscK0 = vK0n - thrK0;
        float zK0n = (vscK0 > 0.f) ? 1.f : 0.f;
        float aK1n = RHO * aK1 + zK1, thrK1 = 1.0f + BETA * aK1n;
        float vK1n = ALPHA * vK1 + accK1 - zK1 * thrK1, vscK1 = vK1n - thrK1;
        float zK1n = (vscK1 > 0.f) ? 1.f : 0.f;
        float aQ0n = RHO * aQ0 + zQ0, thrQ0 = 1.0f + BETA * aQ0n;
        float vQ0n = ALPHA * vQ0 + accQ0 - zQ0 * thrQ0, vscQ0 = vQ0n - thrQ0;
        float zQ0n = (vscQ0 > 0.f) ? 1.f : 0.f;
        float aQ1n = RHO * aQ1 + zQ1, thrQ1 = 1.0f + BETA * aQ1n;
        float vQ1n = ALPHA * vQ1 + accQ1 - zQ1 * thrQ1, vscQ1 = vQ1n - thrQ1;
        float zQ1n = (vscQ1 > 0.f) ? 1.f : 0.f;
        float aV0n = RHO * aV0 + zV0, thrV0 = 1.0f + BETA * aV0n;
        float vV0n = ALPHA * vV0 + accV0 - zV0 * thrV0, vscV0 = vV0n - thrV0;
        float zV0n = (vscV0 > 0.f) ? 1.f : 0.f;
        float aV1n = RHO * aV1 + zV1, thrV1 = 1.0f + BETA * aV1n;
        float vV1n = ALPHA * vV1 + accV1 - zV1 * thrV1, vscV1 = vV1n - thrV1;
        float zV1n = (vscV1 > 0.f) ? 1.f : 0.f;

        unsigned balK0 = __ballot_sync(0xffffffffu, zK0n > 0.f);
        unsigned balK1 = __ballot_sync(0xffffffffu, zK1n > 0.f);
        unsigned balQ0 = __ballot_sync(0xffffffffu, zQ0n > 0.f);
        unsigned balQ1 = __ballot_sync(0xffffffffu, zQ1n > 0.f);
        unsigned balV0 = __ballot_sync(0xffffffffu, zV0n > 0.f);
        unsigned balV1 = __ballot_sync(0xffffffffu, zV1n > 0.f);
        if (lane == 0) {
            ss->mask[0][warp] = balK0;  ss->mask[0][8 + warp] = balK1;
            ss->mask[1][warp] = balQ0;  ss->mask[1][8 + warp] = balQ1;
            ss->mask[2][warp] = balV0;  ss->mask[2][8 + warp] = balV1;
            const unsigned seq = (unsigned)(t + 1);
            push_word(&spkK[(size_t)t * 16 + warp],     seq, balK0);
            push_word(&spkK[(size_t)t * 16 + 8 + warp], seq, balK1);
            push_word(&spkQ[(size_t)t * 16 + warp],     seq, balQ0);
            push_word(&spkQ[(size_t)t * 16 + 8 + warp], seq, balQ1);
            push_word(&spkV[(size_t)t * 16 + warp],     seq, balV0);
            push_word(&spkV[(size_t)t * 16 + 8 + warp], seq, balV1);
        }
        __syncthreads();                                    // B2

        const size_t base = (size_t)b * NT + t;
        __stcs(&out2[base * 3072 + 0 * 512 + u0], zK0n);  __stcs(&out2[base * 3072 + 0 * 512 + u1], zK1n);
        __stcs(&out2[base * 3072 + 1 * 512 + u0], zQ0n);  __stcs(&out2[base * 3072 + 1 * 512 + u1], zQ1n);
        __stcs(&out2[base * 3072 + 2 * 512 + u0], zV0n);  __stcs(&out2[base * 3072 + 2 * 512 + u1], zV1n);
        __stcs(&out3[base * 2048 + 0 * 512 + u0], thrK0); __stcs(&out3[base * 2048 + 0 * 512 + u1], thrK1);
        __stcs(&out3[base * 2048 + 1 * 512 + u0], thrQ0); __stcs(&out3[base * 2048 + 1 * 512 + u1], thrQ1);
        __stcs(&out3[base * 2048 + 2 * 512 + u0], thrV0); __stcs(&out3[base * 2048 + 2 * 512 + u1], thrV1);
        __stcs(&out4[base * 3072 + 0 * 512 + u0], vscK0); __stcs(&out4[base * 3072 + 0 * 512 + u1], vscK1);
        __stcs(&out4[base * 3072 + 1 * 512 + u0], vscQ0); __stcs(&out4[base * 3072 + 1 * 512 + u1], vscQ1);
        __stcs(&out4[base * 3072 + 2 * 512 + u0], vscV0); __stcs(&out4[base * 3072 + 2 * 512 + u1], vscV1);

        vK0 = vK0n; aK0 = aK0n; zK0 = zK0n;  vK1 = vK1n; aK1 = aK1n; zK1 = zK1n;
        vQ0 = vQ0n; aQ0 = aQ0n; zQ0 = zQ0n;  vQ1 = vQ1n; aQ1 = aQ1n; zQ1 = zQ1n;
        vV0 = vV0n; aV0 = aV0n; zV0 = zV0n;  vV1 = vV1n; aV1 = aV1n; zV1 = zV1n;
    }
}

// ---------------------------------------------------------------------------
// WTA role: 256 threads, 2 neurons/thread. 3 bars/step (end barrier removed;
// B1/B2/B3 of step t+1 order every smem reuse against reads at step t).
// ---------------------------------------------------------------------------
__device__ void wta_role(int b, const float* __restrict__ Wa,
                         const float* __restrict__ Wb,
                         float* __restrict__ d_out, ScanSmem* ss)
{
    const unsigned long long* __restrict__ spkK = g_spk64 + (size_t)b * NT * 16;
    const unsigned long long* __restrict__ spkQ = g_spk64 + ((size_t)NB + b) * NT * 16;
    unsigned long long* __restrict__ zAout      = g_zA64 + (size_t)b * NT * 16;

    float* __restrict__ out2 = d_out + OUT2_OFF;
    float* __restrict__ out4 = d_out + OUT4_OFF;

    const int tid = threadIdx.x, warp = tid >> 5, lane = tid & 31;
    const int u0 = tid, u1 = tid + 256;

    float vA0 = 0.f, vB0 = 0.f, zA0 = 0.f, zB0 = 0.f;
    float vA1 = 0.f, vB1 = 0.f, zA1 = 0.f, zB1 = 0.f;

    for (int t = 0; t < NT; t++) {
        if (warp == 0) {
            const unsigned seq = (unsigned)(t + 1);
            unsigned m = (lane < 16) ? poll_word(&spkK[(size_t)t * 16 + lane], seq)
                                     : poll_word(&spkQ[(size_t)t * 16 + (lane - 16)], seq);
            int tot = build_list(m, 0, ss->listKQ, 0);
            if (lane < 8) ss->listKQ[tot + lane] = 0;
            if (lane == 0) ss->totKQ = tot;
        }
        __syncthreads();                                   // B1
        const int nsp = ss->totKQ;

        float acc0 = 0.f, acc1 = 0.f;
        gather8d(Wa, ss->listKQ, nsp, u0, u1, acc0, acc1);

        float vA0n = ALPHA * vA0 + acc0 - zA0;
        float vA1n = ALPHA * vA1 + acc1 - zA1;
        float vscA0 = vA0n - 1.0f, vscA1 = vA1n - 1.0f;

        float mx = fmaxf(vA0n, vA1n);
#pragma unroll
        for (int o = 16; o > 0; o >>= 1) mx = fmaxf(mx, __shfl_xor_sync(0xffffffffu, mx, o));
        if (lane == 0) ss->red[warp] = mx;
        __syncthreads();                                   // B2
        float mm = ss->red[lane & 7];
#pragma unroll
        for (int o = 4; o > 0; o >>= 1) mm = fmaxf(mm, __shfl_xor_sync(0xffffffffu, mm, o));

        float zA0n = (vscA0 > 0.f && vA0n == mm) ? 1.f : 0.f;
        float zA1n = (vscA1 > 0.f && vA1n == mm) ? 1.f : 0.f;

        unsigned balZ0 = __ballot_sync(0xffffffffu, zA0n > 0.f);
        unsigned balZ1 = __ballot_sync(0xffffffffu, zA1n > 0.f);
        if (lane == 0) {
            ss->maskZ[warp]     = balZ0;
            ss->maskZ[8 + warp] = balZ1;
            const unsigned seq = (unsigned)(t + 1);
            push_word(&zAout[(size_t)t * 16 + warp],     seq, balZ0);
            push_word(&zAout[(size_t)t * 16 + 8 + warp], seq, balZ1);
        }
        __syncthreads();                                   // B3

        float accB0 = 0.f, accB1 = 0.f;
#pragma unroll
        for (int w = 0; w < 16; w++) {
            unsigned mb = ss->maskZ[w];
            while (mb) {
                int j = __ffs((int)mb) - 1;
                size_t r = (size_t)(w * 32 + j) * 512;
                accB0 += Wb[r + u0];
                accB1 += Wb[r + u1];
                mb &= mb - 1;
            }
        }
        float vB0n = ALPHA * vB0 + accB0 - zB0, vscB0 = vB0n - 1.0f;
        float zB0n = (vscB0 > 0.f) ? 1.f : 0.f;
        float vB1n = ALPHA * vB1 + accB1 - zB1, vscB1 = vB1n - 1.0f;
        float zB1n = (vscB1 > 0.f) ? 1.f : 0.f;

        const size_t base = (size_t)b * NT + t;
        __stcs(&out2[base * 3072 + 3 * 512 + u0], zA0n);  __stcs(&out2[base * 3072 + 3 * 512 + u1], zA1n);
        __stcs(&out2[base * 3072 + 4 * 512 + u0], zB0n);  __stcs(&out2[base * 3072 + 4 * 512 + u1], zB1n);
        __stcs(&out4[base * 3072 + 3 * 512 + u0], vscA0); __stcs(&out4[base * 3072 + 3 * 512 + u1], vscA1);
        __stcs(&out4[base * 3072 + 4 * 512 + u0], vscB0); __stcs(&out4[base * 3072 + 4 * 512 + u1], vscB1);

        vA0 = vA0n; vB0 = vB0n; zA0 = zA0n; zB0 = zB0n;
        vA1 = vA1n; vB1 = vB1n; zA1 = zA1n; zB1 = zB1n;
        // no end barrier: B1/B2/B3 of step t+1 order all smem reuse
    }
}

// ---------------------------------------------------------------------------
// Attention LSNN role: 256 threads, 2 neurons/thread. 2 bars/step.
// ---------------------------------------------------------------------------
__device__ void att_role(int b, const float* __restrict__ Win,
                         const float* __restrict__ Wrec,
                         float* __restrict__ d_out, ScanSmem* ss)
{
    const unsigned long long* __restrict__ spkV = g_spk64 + ((size_t)2 * NB + b) * NT * 16;
    const unsigned long long* __restrict__ zAin = g_zA64 + (size_t)b * NT * 16;

    float* __restrict__ out1 = d_out + OUT1_OFF;
    float* __restrict__ out2 = d_out + OUT2_OFF;
    float* __restrict__ out3 = d_out + OUT3_OFF;
    float* __restrict__ out4 = d_out + OUT4_OFF;

    const int tid = threadIdx.x, warp = tid >> 5, lane = tid & 31;
    const int u0 = tid, u1 = tid + 256;

    if (tid < 16) ss->maskR[tid] = 0u;
    __syncthreads();

    float v0 = 0.f, a0 = 0.f, z0 = 0.f;
    float v1 = 0.f, a1 = 0.f, z1 = 0.f;

    for (int t = 0; t < NT; t++) {
        if (warp == 0) {
            const unsigned seq = (unsigned)(t + 1);
            unsigned m1 = (lane < 16) ? poll_word(&spkV[(size_t)t * 16 + lane], seq)
                                      : poll_word(&zAin[(size_t)t * 16 + (lane - 16)], seq);
            int t1 = build_list(m1, 0, ss->listAtt, 0);
            unsigned m2 = (lane < 16) ? ss->maskR[lane] : 0u;
            int t2 = build_list(m2, 1024, ss->listAtt, t1);
            int tot = t1 + t2;
            if (lane < 8) ss->listAtt[tot + lane] = 0;
            if (lane == 0) ss->totAtt = tot;
        }
        __syncthreads();                                   // B1
        const int nsp = ss->totAtt;

        float acc0 = 0.f, acc1 = 0.f;
        gather8d_2(Win, Wrec, ss->listAtt, nsp, u0, u1, acc0, acc1);

        float a0n = RHO * a0 + z0, thr0 = 1.0f + BETA * a0n;
        float v0n = ALPHA * v0 + acc0 - z0 * thr0, vsc0 = v0n - thr0;
        float z0n = (vsc0 > 0.f) ? 1.f : 0.f;
        float a1n = RHO * a1 + z1, thr1 = 1.0f + BETA * a1n;
        float v1n = ALPHA * v1 + acc1 - z1 * thr1, vsc1 = v1n - thr1;
        float z1n = (vsc1 > 0.f) ? 1.f : 0.f;

        unsigned bal0 = __ballot_sync(0xffffffffu, z0n > 0.f);
        unsigned bal1 = __ballot_sync(0xffffffffu, z1n > 0.f);
        if (lane == 0) {
            ss->maskR[warp]     = bal0;
            ss->maskR[8 + warp] = bal1;
        }

        const size_t base = (size_t)b * NT + t;
        __stcs(&out1[base * 512 + u0], z0n);             __stcs(&out1[base * 512 + u1], z1n);
        __stcs(&out2[base * 3072 + 5 * 512 + u0], z0n);  __stcs(&out2[base * 3072 + 5 * 512 + u1], z1n);
        __stcs(&out3[base * 2048 + 3 * 512 + u0], thr0); __stcs(&out3[base * 2048 + 3 * 512 + u1], thr1);
        __stcs(&out4[base * 3072 + 5 * 512 + u0], vsc0); __stcs(&out4[base * 3072 + 5 * 512 + u1], vsc1);

        v0 = v0n; a0 = a0n; z0 = z0n;
        v1 = v1n; a1 = a1n; z1 = z1n;
        __syncthreads();                                   // B2 (protects maskR)
    }
}

// ---------------------------------------------------------------------------
__global__ __launch_bounds__(256, 2) void fused_kernel(
    const float* __restrict__ Wk_in, const float* __restrict__ Wk_rec,
    const float* __restrict__ Wq_in, const float* __restrict__ Wq_rec,
    const float* __restrict__ Wv_in, const float* __restrict__ Wv_rec,
    const float* __restrict__ Watt_in, const float* __restrict__ Watt_rec,
    const float* __restrict__ Wwta_a, const float* __restrict__ Wwta_b,
    float* __restrict__ d_out)
{
    __shared__ __align__(16) unsigned char smem_raw[
        sizeof(GemmSmem) > sizeof(ScanSmem) ? sizeof(GemmSmem) : sizeof(ScanSmem)];
    const int bid = blockIdx.x;

    if (bid >= 96) {
        gemm_role(bid - 96, Wk_in, Wq_in, Wv_in, (GemmSmem*)smem_raw);
        return;
    }
    ScanSmem* ss = (ScanSmem*)smem_raw;
    if (bid < 32) {
        kqv_role(bid, Wk_rec, Wq_rec, Wv_rec, d_out, ss);
    } else if (bid < 64) {
        wta_role(bid - 32, Wwta_a, Wwta_b, d_out, ss);
    } else {
        att_role(bid - 64, Watt_in, Watt_rec, d_out, ss);
    }
}

// ---------------------------------------------------------------------------
extern "C" void kernel_launch(void* const* d_in, const int* in_sizes, int n_in,
                              void* d_out, int out_size)
{
    const float* x        = (const float*)d_in[0];
    const float* Wk_in    = (const float*)d_in[1];
    const float* Wk_rec   = (const float*)d_in[2];
    const float* Wq_in    = (const float*)d_in[3];
    const float* Wq_rec   = (const float*)d_in[4];
    const float* Wv_in    = (const float*)d_in[5];
    const float* Wv_rec   = (const float*)d_in[6];
    const float* Watt_in  = (const float*)d_in[7];
    const float* Watt_rec = (const float*)d_in[8];
    const float* Wwta_a   = (const float*)d_in[9];
    const float* Wwta_b   = (const float*)d_in[10];
    float* out = (float*)d_out;

    (void)in_sizes; (void)n_in; (void)out_size;

    dim3 gT(1000, 4);
    transpose_kernel<<<gT, 256>>>(x);
    reset_kernel<<<512, 512>>>();
    fused_kernel<<<96 + 3000, 256>>>(Wk_in, Wk_rec, Wq_in, Wq_rec,
                                     Wv_in, Wv_rec, Watt_in, Watt_rec,
                                     Wwta_a, Wwta_b, out);
}